// round 13
// baseline (speedup 1.0000x reference)
#include <cuda_runtime.h>
#include <cstdint>

// Sparse ConvTranspose3d on GB300 (sm_103a) — mma.sync tf32 tensor cores.
//   out[r,:] = bias + sum_{(k,n): out_index[k,n]==r} feats[n,:] @ weight[k,:,:]^T
//
// R13 = R12 with occupancy + pre-pass fixes:
//  - TILE_N=256 / 256 threads / __launch_bounds__(256,2): 16 warps/SM (was 12),
//    same per-warp fragment shape and epilogue as R12.
//  - cond_bias_init coalesced (thread per float4, not per row).
//  - fragment-major prepack (R12) and cout permutation (R11) unchanged.

#define CIN    64
#define COUT   64
#define TILE_N 256
#define KCHUNK 9
#define MAX_ROWS (60000 * 27)
#define N_PAD  60160                       // 235 * 256
#define NT128  (N_PAD / 128)               // 470 prepacked 128-pt tiles

__device__ int   g_counts[MAX_ROWS];
__device__ float g_feats_f[N_PAD * CIN];        // fragment-major feats (tf32)
__device__ float g_weight_f[27 * COUT * CIN];   // fragment-major, cout-permuted

// ---------------------------------------------------------------- pre-pass ----
__global__ void zero_counts_kernel(int n4) {
    int i = blockIdx.x * blockDim.x + threadIdx.x;
    if (i < n4) reinterpret_cast<int4*>(g_counts)[i] = make_int4(0, 0, 0, 0);
}
__global__ void count_kernel(const int* __restrict__ oi, int total) {
    int i = blockIdx.x * blockDim.x + threadIdx.x;
    if (i < total) atomicAdd(&g_counts[oi[i]], 1);
}
// coalesced: one float4 per thread; rows with count!=1 get bias
__global__ void cond_bias_init_kernel(const float4* __restrict__ bias4,
                                      float4* __restrict__ out4, int tot4) {
    int i = blockIdx.x * blockDim.x + threadIdx.x;
    if (i >= tot4) return;
    int r = i >> 4;
    if (__ldg(&g_counts[r]) != 1) out4[i] = bias4[i & 15];
}

__device__ __forceinline__ uint32_t to_tf32(float f) {
    uint32_t u;
    asm("cvt.rna.tf32.f32 %0, %1;" : "=r"(u) : "f"(f));
    return u;
}

// feats -> fragment-major 128-pt tiles: slot i = (tile, mi, kc, lane), 4 floats:
//   lane=(g,t): { A[16mi+g][8kc+t], A[16mi+8+g][8kc+t],
//                 A[16mi+g][8kc+t+4], A[16mi+8+g][8kc+t+4] }   (rows rel. tile)
__global__ void prep_feats_kernel(const float* __restrict__ feats, int N, int tot) {
    int i = blockIdx.x * blockDim.x + threadIdx.x;
    if (i >= tot) return;                       // tot = NT128*2048
    int lane = i & 31;
    int kc   = (i >> 5) & 7;
    int mi   = (i >> 8) & 7;
    int tile = i >> 11;
    int g = lane >> 2, t = lane & 3;
    int r0 = tile * 128 + mi * 16 + g;
    int r1 = r0 + 8;
    int c0 = kc * 8 + t;
    float v0 = (r0 < N) ? feats[(size_t)r0 * CIN + c0]     : 0.f;
    float v1 = (r1 < N) ? feats[(size_t)r1 * CIN + c0]     : 0.f;
    float v2 = (r0 < N) ? feats[(size_t)r0 * CIN + c0 + 4] : 0.f;
    float v3 = (r1 < N) ? feats[(size_t)r1 * CIN + c0 + 4] : 0.f;
    uint4 o = make_uint4(to_tf32(v0), to_tf32(v1), to_tf32(v2), to_tf32(v3));
    reinterpret_cast<uint4*>(g_feats_f)[i] = o;
}

// weight -> fragment-major + cout permutation L(f) (see R11/R12)
__device__ __forceinline__ int Lperm(int f) {
    int nt = f >> 3, ct = f & 7;
    return 16 * (nt >> 1) + 2 * (nt & 1) + 4 * (ct >> 1) + (ct & 1);
}
__global__ void prep_weight_kernel(const float* __restrict__ w, int tot) {
    int i = blockIdx.x * blockDim.x + threadIdx.x;
    if (i >= tot) return;                       // tot = 27*1024
    int lane = i & 31;
    int m    = (i >> 5) & 3;
    int kc   = (i >> 7) & 7;
    int k    = i >> 10;
    int g = lane >> 2, t = lane & 3;
    int f0 = 8 * (2 * m)     + g;
    int f1 = 8 * (2 * m + 1) + g;
    const float* wk = w + (size_t)k * COUT * CIN;
    int c0 = kc * 8 + t;
    float v0 = wk[Lperm(f0) * CIN + c0];
    float v1 = wk[Lperm(f0) * CIN + c0 + 4];
    float v2 = wk[Lperm(f1) * CIN + c0];
    float v3 = wk[Lperm(f1) * CIN + c0 + 4];
    uint4 o = make_uint4(to_tf32(v0), to_tf32(v1), to_tf32(v2), to_tf32(v3));
    reinterpret_cast<uint4*>(g_weight_f)[i] = o;
}

// ---------------------------------------------------------------- helpers ----
__device__ __forceinline__ uint32_t f2u(float f) { return __float_as_uint(f); }

__device__ __forceinline__ void mma_tf32(float c[4], const uint32_t a[4],
                                         uint32_t b0, uint32_t b1) {
    asm volatile(
        "mma.sync.aligned.m16n8k8.row.col.f32.tf32.tf32.f32 "
        "{%0,%1,%2,%3}, {%4,%5,%6,%7}, {%8,%9}, {%0,%1,%2,%3};"
        : "+f"(c[0]), "+f"(c[1]), "+f"(c[2]), "+f"(c[3])
        : "r"(a[0]), "r"(a[1]), "r"(a[2]), "r"(a[3]), "r"(b0), "r"(b1));
}

__device__ __forceinline__ void cp16(float* smem_dst, const float* gsrc) {
    unsigned d = (unsigned)__cvta_generic_to_shared(smem_dst);
    asm volatile("cp.async.cg.shared.global [%0], [%1], 16;\n"
                 :: "r"(d), "l"(gsrc));
}

// ------------------------------------------------------------- main kernel ----
// dyn smem (floats): As[16384] (64KB: two 128-pt fragment tiles) | Wb[2 x 4096]
#define A_FLOATS 16384
#define W_FLOATS 4096

__global__ void __launch_bounds__(256, 2) spconvt_mma_kernel(
    const float* __restrict__ bias,      // [64]
    const int*   __restrict__ out_index, // [27, N]
    float*       __restrict__ out,       // [n_out, 64]
    int N, int KV)
{
    extern __shared__ float smem[];
    float* As = smem;                        // 2 x 8192 fragment-major A tiles
    float* Wb = smem + A_FLOATS;             // 2 fragment-major W buffers

    const int tid  = threadIdx.x;
    const int w    = tid >> 5;               // warp 0..7
    const int lane = tid & 31;
    const int g    = lane >> 2;
    const int t    = lane & 3;
    const int n0   = blockIdx.x * TILE_N;
    const int k0   = blockIdx.y * KCHUNK;

    // ---- A: straight 64KB async copy of two prepacked tiles ----
    {
        const float* src = g_feats_f + (size_t)blockIdx.x * A_FLOATS;
        #pragma unroll
        for (int j = 0; j < 16; j++) {
            int idx = tid + 256 * j;          // 0..4095 float4 slots
            cp16(As + idx * 4, src + idx * 4);
        }
    }
    // ---- W[k] loader: straight 16KB async copy ----
    auto cpW = [&](int k, int b) {
        const float* src = g_weight_f + (size_t)k * W_FLOATS;
        float* dst = Wb + b * W_FLOATS;
        #pragma unroll
        for (int j = 0; j < 4; j++) {
            int idx = tid + 256 * j;          // 0..1023
            cp16(dst + idx * 4, src + idx * 4);
        }
        asm volatile("cp.async.commit_group;\n");
    };
    cpW(k0, 0);

    // per-thread bias float4s: logical couts [16m+4t, +4) -> bias4[4m + t]
    float4 b4[4];
    #pragma unroll
    for (int m = 0; m < 4; m++)
        b4[m] = __ldg(reinterpret_cast<const float4*>(bias) + 4 * m + t);

    asm volatile("cp.async.wait_group 0;\n" ::: "memory");
    __syncthreads();

    // warp w owns m16 tiles 2w, 2w+1 (rows [32w, 32w+32) of the 256-pt tile)
    const int p0 = 32 * w + g;
    // A fragment base offsets for mt=0,1: tile128 = (2w+mt)>>3, mi = (2w+mt)&7
    int abase[2];
    #pragma unroll
    for (int mt = 0; mt < 2; mt++) {
        int m16 = 2 * w + mt;
        abase[mt] = ((m16 >> 3) * 8192) + ((m16 & 7) * 8) * 32 * 4;  // + kc*32*4
    }

    int buf = 0;

    for (int kk = 0; kk < KCHUNK; kk++) {
        int k = k0 + kk;
        if (k >= KV) break;
        bool more = (kk + 1 < KCHUNK) && (k + 1 < KV);

        if (more) cpW(k + 1, buf ^ 1);

        // prefetch scatter metadata for the 4 owned rows (p0 + 8j)
        int rrv[4], cntv[4];
        #pragma unroll
        for (int j = 0; j < 4; j++) {
            int n = n0 + p0 + 8 * j;
            rrv[j]  = (n < N) ? __ldg(out_index + (size_t)k * N + n) : -1;
            cntv[j] = (rrv[j] >= 0) ? __ldg(&g_counts[rrv[j]]) : 0;
        }

        const float* Wc = Wb + buf * W_FLOATS;

        float acc[2][8][4];
        #pragma unroll
        for (int mt = 0; mt < 2; mt++)
            #pragma unroll
            for (int nt = 0; nt < 8; nt++)
                #pragma unroll
                for (int x = 0; x < 4; x++) acc[mt][nt][x] = 0.f;

        #pragma unroll
        for (int kc = 0; kc < 8; kc++) {
            uint32_t a[2][4];
            #pragma unroll
            for (int mt = 0; mt < 2; mt++) {
                float4 av = *reinterpret_cast<const float4*>(
                    As + abase[mt] + (kc * 32 + lane) * 4);
                a[mt][0] = f2u(av.x); a[mt][1] = f2u(av.y);
                a[mt][2] = f2u(av.z); a[mt][3] = f2u(av.w);
            }
            #pragma unroll
            for (int m = 0; m < 4; m++) {
                float4 bv = *reinterpret_cast<const float4*>(
                    Wc + ((kc * 4 + m) * 32 + lane) * 4);
                uint32_t b0a = f2u(bv.x), b1a = f2u(bv.y);   // nt = 2m
                uint32_t b0b = f2u(bv.z), b1b = f2u(bv.w);   // nt = 2m+1
                mma_tf32(acc[0][2 * m],     a[0], b0a, b1a);
                mma_tf32(acc[1][2 * m],     a[1], b0a, b1a);
                mma_tf32(acc[0][2 * m + 1], a[0], b0b, b1b);
                mma_tf32(acc[1][2 * m + 1], a[1], b0b, b1b);
            }
        }

        // ---- scatter epilogue (R11/R12 v4 form) ----
        #pragma unroll
        for (int j = 0; j < 4; j++) {
            if (rrv[j] < 0) continue;
            const int mt = j >> 1, hi = (j & 1) * 2;
            float* dst = out + (size_t)rrv[j] * COUT + 4 * t;
            if (cntv[j] == 1) {
                #pragma unroll
                for (int m = 0; m < 4; m++) {
                    float4 v = make_float4(acc[mt][2*m][hi]       + b4[m].x,
                                           acc[mt][2*m][hi + 1]   + b4[m].y,
                                           acc[mt][2*m+1][hi]     + b4[m].z,
                                           acc[mt][2*m+1][hi + 1] + b4[m].w);
                    *reinterpret_cast<float4*>(dst + 16 * m) = v;
                }
            } else {
                #pragma unroll
                for (int m = 0; m < 4; m++) {
                    asm volatile("red.global.add.v4.f32 [%0], {%1, %2, %3, %4};"
                                 :: "l"(dst + 16 * m),
                                    "f"(acc[mt][2*m][hi]),
                                    "f"(acc[mt][2*m][hi + 1]),
                                    "f"(acc[mt][2*m+1][hi]),
                                    "f"(acc[mt][2*m+1][hi + 1])
                                 : "memory");
                }
            }
        }

        asm volatile("cp.async.wait_group 0;\n" ::: "memory");
        __syncthreads();
        buf ^= 1;
    }
}

extern "C" void kernel_launch(void* const* d_in, const int* in_sizes, int n_in,
                              void* d_out, int out_size) {
    const float* feats     = (const float*)d_in[0];   // [N, 64]
    const float* weight    = (const float*)d_in[1];   // [27, 64, 64]
    const float* bias      = (const float*)d_in[2];   // [64]
    const int*   out_index = (const int*)d_in[3];     // [27, N]
    float* out = (float*)d_out;                        // [n_out, 64]

    int N  = in_sizes[0] / CIN;
    int KV = in_sizes[1] / (COUT * CIN);
    int n_out = out_size / COUT;
    int total_idx = in_sizes[3];                       // KV * N

    int z4 = (n_out + 3) / 4;
    zero_counts_kernel<<<(z4 + 255) / 256, 256>>>(z4);
    count_kernel<<<(total_idx + 255) / 256, 256>>>(out_index, total_idx);
    int tot4 = out_size / 4;                           // n_out * 16
    cond_bias_init_kernel<<<(tot4 + 255) / 256, 256>>>(
        (const float4*)bias, (float4*)out, tot4);

    // fragment-major prepack
    int tot_a = NT128 * 2048;
    prep_feats_kernel<<<(tot_a + 255) / 256, 256>>>(feats, N, tot_a);
    int tot_w = KV * 1024;
    prep_weight_kernel<<<(tot_w + 255) / 256, 256>>>(weight, tot_w);

    const int smem_bytes = (A_FLOATS + 2 * W_FLOATS) * sizeof(float);  // 96KB
    cudaFuncSetAttribute(spconvt_mma_kernel,
                         cudaFuncAttributeMaxDynamicSharedMemorySize, smem_bytes);
    dim3 grid((N + TILE_N - 1) / TILE_N, (KV + KCHUNK - 1) / KCHUNK);
    spconvt_mma_kernel<<<grid, 256, smem_bytes>>>(bias, out_index, out, N, KV);
}

// round 14
// speedup vs baseline: 1.1608x; 1.1608x over previous
#include <cuda_runtime.h>
#include <cstdint>

// Sparse ConvTranspose3d on GB300 (sm_103a) — mma.sync tf32 tensor cores.
//   out[r,:] = bias + sum_{(k,n): out_index[k,n]==r} feats[n,:] @ weight[k,:,:]^T
//
// R14 = R12 base (TILE_N=128, 128 thr, 3 blocks/SM) with A HOISTED TO REGISTERS:
//   A is invariant across the 9 k-offsets a block processes, so each warp loads
//   its 16 fragment float4s once from prepacked gmem (coalesced LDG.128) and
//   keeps them in registers. Removes 64 smem wavefronts + 16 LDS issues per
//   warp-k and the 32KB A smem tile. SMEM now holds only the W double buffer.
//   Fragment-major prepack (R12) + cout permutation (R11) unchanged.

#define CIN    64
#define COUT   64
#define TILE_N 128
#define KCHUNK 9
#define MAX_ROWS (60000 * 27)
#define N_PAD  60160                       // 470 * 128 >= N
#define NT128  (N_PAD / 128)               // 470 prepacked tiles

__device__ int   g_counts[MAX_ROWS];
__device__ float g_feats_f[N_PAD * CIN];        // fragment-major feats (tf32)
__device__ float g_weight_f[27 * COUT * CIN];   // fragment-major, cout-permuted

// ---------------------------------------------------------------- pre-pass ----
__global__ void zero_counts_kernel(int n4) {
    int i = blockIdx.x * blockDim.x + threadIdx.x;
    if (i < n4) reinterpret_cast<int4*>(g_counts)[i] = make_int4(0, 0, 0, 0);
}
__global__ void count_kernel(const int* __restrict__ oi, int total) {
    int i = blockIdx.x * blockDim.x + threadIdx.x;
    if (i < total) atomicAdd(&g_counts[oi[i]], 1);
}
__global__ void cond_bias_init_kernel(const float4* __restrict__ bias4,
                                      float4* __restrict__ out4, int n_out) {
    int r = blockIdx.x * blockDim.x + threadIdx.x;
    if (r < n_out && g_counts[r] != 1) {
        #pragma unroll
        for (int j = 0; j < 16; j++) out4[(size_t)r * 16 + j] = bias4[j];
    }
}

__device__ __forceinline__ uint32_t to_tf32(float f) {
    uint32_t u;
    asm("cvt.rna.tf32.f32 %0, %1;" : "=r"(u) : "f"(f));
    return u;
}

// feats -> fragment-major: slot i = (tile, mi, kc, lane); 4 floats:
//   lane=(g,t): { A[16mi+g][8kc+t], A[16mi+8+g][8kc+t],
//                 A[16mi+g][8kc+t+4], A[16mi+8+g][8kc+t+4] }   (rows rel. tile)
__global__ void prep_feats_kernel(const float* __restrict__ feats, int N, int tot) {
    int i = blockIdx.x * blockDim.x + threadIdx.x;
    if (i >= tot) return;                       // tot = NT128*2048
    int lane = i & 31;
    int kc   = (i >> 5) & 7;
    int mi   = (i >> 8) & 7;
    int tile = i >> 11;
    int g = lane >> 2, t = lane & 3;
    int r0 = tile * 128 + mi * 16 + g;
    int r1 = r0 + 8;
    int c0 = kc * 8 + t;
    float v0 = (r0 < N) ? feats[(size_t)r0 * CIN + c0]     : 0.f;
    float v1 = (r1 < N) ? feats[(size_t)r1 * CIN + c0]     : 0.f;
    float v2 = (r0 < N) ? feats[(size_t)r0 * CIN + c0 + 4] : 0.f;
    float v3 = (r1 < N) ? feats[(size_t)r1 * CIN + c0 + 4] : 0.f;
    uint4 o = make_uint4(to_tf32(v0), to_tf32(v1), to_tf32(v2), to_tf32(v3));
    reinterpret_cast<uint4*>(g_feats_f)[i] = o;
}

// weight -> fragment-major + cout permutation L(f) (see R11/R12)
__device__ __forceinline__ int Lperm(int f) {
    int nt = f >> 3, ct = f & 7;
    return 16 * (nt >> 1) + 2 * (nt & 1) + 4 * (ct >> 1) + (ct & 1);
}
__global__ void prep_weight_kernel(const float* __restrict__ w, int tot) {
    int i = blockIdx.x * blockDim.x + threadIdx.x;
    if (i >= tot) return;                       // tot = 27*1024
    int lane = i & 31;
    int m    = (i >> 5) & 3;
    int kc   = (i >> 7) & 7;
    int k    = i >> 10;
    int g = lane >> 2, t = lane & 3;
    int f0 = 8 * (2 * m)     + g;
    int f1 = 8 * (2 * m + 1) + g;
    const float* wk = w + (size_t)k * COUT * CIN;
    int c0 = kc * 8 + t;
    float v0 = wk[Lperm(f0) * CIN + c0];
    float v1 = wk[Lperm(f0) * CIN + c0 + 4];
    float v2 = wk[Lperm(f1) * CIN + c0];
    float v3 = wk[Lperm(f1) * CIN + c0 + 4];
    uint4 o = make_uint4(to_tf32(v0), to_tf32(v1), to_tf32(v2), to_tf32(v3));
    reinterpret_cast<uint4*>(g_weight_f)[i] = o;
}

// ---------------------------------------------------------------- helpers ----
__device__ __forceinline__ uint32_t f2u(float f) { return __float_as_uint(f); }

__device__ __forceinline__ void mma_tf32(float c[4], const uint32_t a[4],
                                         uint32_t b0, uint32_t b1) {
    asm volatile(
        "mma.sync.aligned.m16n8k8.row.col.f32.tf32.tf32.f32 "
        "{%0,%1,%2,%3}, {%4,%5,%6,%7}, {%8,%9}, {%0,%1,%2,%3};"
        : "+f"(c[0]), "+f"(c[1]), "+f"(c[2]), "+f"(c[3])
        : "r"(a[0]), "r"(a[1]), "r"(a[2]), "r"(a[3]), "r"(b0), "r"(b1));
}

__device__ __forceinline__ void cp16(float* smem_dst, const float* gsrc) {
    unsigned d = (unsigned)__cvta_generic_to_shared(smem_dst);
    asm volatile("cp.async.cg.shared.global [%0], [%1], 16;\n"
                 :: "r"(d), "l"(gsrc));
}

// ------------------------------------------------------------- main kernel ----
// dyn smem (floats): Wb[2 x 4096] = 32KB (W double buffer only)
#define W_FLOATS 4096

__global__ void __launch_bounds__(128, 3) spconvt_mma_kernel(
    const float* __restrict__ bias,      // [64]
    const int*   __restrict__ out_index, // [27, N]
    float*       __restrict__ out,       // [n_out, 64]
    int N, int KV)
{
    extern __shared__ float smem[];
    float* Wb = smem;                        // 2 fragment-major W buffers

    const int tid  = threadIdx.x;
    const int w    = tid >> 5;
    const int lane = tid & 31;
    const int g    = lane >> 2;
    const int t    = lane & 3;
    const int n0   = blockIdx.x * TILE_N;
    const int k0   = blockIdx.y * KCHUNK;

    // ---- W[k] loader: straight 16KB async copy ----
    auto cpW = [&](int k, int b) {
        const float* src = g_weight_f + (size_t)k * W_FLOATS;
        float* dst = Wb + b * W_FLOATS;
        #pragma unroll
        for (int j = 0; j < 8; j++) {
            int idx = tid + 128 * j;          // 0..1023
            cp16(dst + idx * 4, src + idx * 4);
        }
        asm volatile("cp.async.commit_group;\n");
    };
    cpW(k0, 0);

    // ---- A fragments: one coalesced LDG.128 burst, resident in registers ----
    // slot (tile=blockIdx.x, mi=2w+mt, kc, lane)
    uint32_t areg[2][8][4];
    {
        const float4* asrc = reinterpret_cast<const float4*>(g_feats_f)
                           + (size_t)blockIdx.x * 2048;
        #pragma unroll
        for (int mt = 0; mt < 2; mt++) {
            int mi = 2 * w + mt;
            #pragma unroll
            for (int kc = 0; kc < 8; kc++) {
                float4 av = __ldg(&asrc[(mi * 8 + kc) * 32 + lane]);
                areg[mt][kc][0] = f2u(av.x); areg[mt][kc][1] = f2u(av.y);
                areg[mt][kc][2] = f2u(av.z); areg[mt][kc][3] = f2u(av.w);
            }
        }
    }

    // per-thread bias float4s: logical couts [16m+4t, +4) -> bias4[4m + t]
    float4 b4[4];
    #pragma unroll
    for (int m = 0; m < 4; m++)
        b4[m] = __ldg(reinterpret_cast<const float4*>(bias) + 4 * m + t);

    asm volatile("cp.async.wait_group 0;\n" ::: "memory");
    __syncthreads();

    const int p0 = 32 * w + g;                // first of 4 owned point rows
    int buf = 0;

    for (int kk = 0; kk < KCHUNK; kk++) {
        int k = k0 + kk;
        if (k >= KV) break;
        bool more = (kk + 1 < KCHUNK) && (k + 1 < KV);

        if (more) cpW(k + 1, buf ^ 1);

        // prefetch scatter metadata
        int rrv[4], cntv[4];
        #pragma unroll
        for (int j = 0; j < 4; j++) {
            int n = n0 + p0 + 8 * j;
            rrv[j]  = (n < N) ? __ldg(out_index + (size_t)k * N + n) : -1;
            cntv[j] = (rrv[j] >= 0) ? __ldg(&g_counts[rrv[j]]) : 0;
        }

        const float* Wc = Wb + buf * W_FLOATS;

        float acc[2][8][4];
        #pragma unroll
        for (int mt = 0; mt < 2; mt++)
            #pragma unroll
            for (int nt = 0; nt < 8; nt++)
                #pragma unroll
                for (int x = 0; x < 4; x++) acc[mt][nt][x] = 0.f;

        #pragma unroll
        for (int kc = 0; kc < 8; kc++) {
            #pragma unroll
            for (int m = 0; m < 4; m++) {
                float4 bv = *reinterpret_cast<const float4*>(
                    Wc + ((kc * 4 + m) * 32 + lane) * 4);
                uint32_t b0a = f2u(bv.x), b1a = f2u(bv.y);   // nt = 2m
                uint32_t b0b = f2u(bv.z), b1b = f2u(bv.w);   // nt = 2m+1
                mma_tf32(acc[0][2 * m],     areg[0][kc], b0a, b1a);
                mma_tf32(acc[1][2 * m],     areg[1][kc], b0a, b1a);
                mma_tf32(acc[0][2 * m + 1], areg[0][kc], b0b, b1b);
                mma_tf32(acc[1][2 * m + 1], areg[1][kc], b0b, b1b);
            }
        }

        // ---- scatter epilogue (R11/R12 v4 form) ----
        #pragma unroll
        for (int j = 0; j < 4; j++) {
            if (rrv[j] < 0) continue;
            const int mt = j >> 1, hi = (j & 1) * 2;
            float* dst = out + (size_t)rrv[j] * COUT + 4 * t;
            if (cntv[j] == 1) {
                #pragma unroll
                for (int m = 0; m < 4; m++) {
                    float4 v = make_float4(acc[mt][2*m][hi]       + b4[m].x,
                                           acc[mt][2*m][hi + 1]   + b4[m].y,
                                           acc[mt][2*m+1][hi]     + b4[m].z,
                                           acc[mt][2*m+1][hi + 1] + b4[m].w);
                    *reinterpret_cast<float4*>(dst + 16 * m) = v;
                }
            } else {
                #pragma unroll
                for (int m = 0; m < 4; m++) {
                    asm volatile("red.global.add.v4.f32 [%0], {%1, %2, %3, %4};"
                                 :: "l"(dst + 16 * m),
                                    "f"(acc[mt][2*m][hi]),
                                    "f"(acc[mt][2*m][hi + 1]),
                                    "f"(acc[mt][2*m+1][hi]),
                                    "f"(acc[mt][2*m+1][hi + 1])
                                 : "memory");
                }
            }
        }

        asm volatile("cp.async.wait_group 0;\n" ::: "memory");
        __syncthreads();
        buf ^= 1;
    }
}

extern "C" void kernel_launch(void* const* d_in, const int* in_sizes, int n_in,
                              void* d_out, int out_size) {
    const float* feats     = (const float*)d_in[0];   // [N, 64]
    const float* weight    = (const float*)d_in[1];   // [27, 64, 64]
    const float* bias      = (const float*)d_in[2];   // [64]
    const int*   out_index = (const int*)d_in[3];     // [27, N]
    float* out = (float*)d_out;                        // [n_out, 64]

    int N  = in_sizes[0] / CIN;
    int KV = in_sizes[1] / (COUT * CIN);
    int n_out = out_size / COUT;
    int total_idx = in_sizes[3];                       // KV * N

    int z4 = (n_out + 3) / 4;
    zero_counts_kernel<<<(z4 + 255) / 256, 256>>>(z4);
    count_kernel<<<(total_idx + 255) / 256, 256>>>(out_index, total_idx);
    cond_bias_init_kernel<<<(n_out + 255) / 256, 256>>>(
        (const float4*)bias, (float4*)out, n_out);

    // fragment-major prepack
    int tot_a = NT128 * 2048;
    prep_feats_kernel<<<(tot_a + 255) / 256, 256>>>(feats, N, tot_a);
    int tot_w = KV * 1024;
    prep_weight_kernel<<<(tot_w + 255) / 256, 256>>>(weight, tot_w);

    const int smem_bytes = 2 * W_FLOATS * sizeof(float);   // 32KB
    cudaFuncSetAttribute(spconvt_mma_kernel,
                         cudaFuncAttributeMaxDynamicSharedMemorySize, smem_bytes);
    dim3 grid((N + TILE_N - 1) / TILE_N, (KV + KCHUNK - 1) / KCHUNK);
    spconvt_mma_kernel<<<grid, 128, smem_bytes>>>(bias, out_index, out, N, KV);
}